// round 3
// baseline (speedup 1.0000x reference)
#include <cuda_runtime.h>

// Float32HardwareSurrogate: per 8x8 image
//   patches(4,16) = quadrants TL,TR,BL,BR each flattened row-major
//   acc1 = relu(patches @ W_conv)            (4,4)
//   c    = clip(acc1/64, -128, 127)          flattened row-major to 16
//   acc2 = c @ W_linear                      (4,)
//   out  = clip(acc2/64, -128, 127)
//
// Streaming-bound: 512MB in, 32MB out. Strategy: coalesced LDG.128 -> padded
// SMEM tile -> per-thread compute -> coalesced STG.128.

#define THREADS 128
#define IMGS_PER_BLOCK 128   // one image per thread
#define F4_PER_IMG 16        // 64 floats
#define IMG_STRIDE4 17       // +1 float4 pad: conflict-free per-thread reads

__device__ __forceinline__ float clip_s8(float v) {
    return fminf(fmaxf(v, -128.0f), 127.0f);
}

__global__ void __launch_bounds__(THREADS)
surrogate_kernel(const float* __restrict__ img1,
                 const float* __restrict__ img2,
                 const float* __restrict__ Wc,
                 const float* __restrict__ Wl,
                 float* __restrict__ out,
                 int nimg)   // images per input tensor (B)
{
    __shared__ float4 simg[IMGS_PER_BLOCK * IMG_STRIDE4];  // ~34.8 KB
    __shared__ float4 sWc[16];   // W_conv rows: sWc[i] = {Wc[i][0..3]}
    __shared__ float4 sWl[16];   // W_linear rows

    const int tid = threadIdx.x;
    const long g0 = (long)blockIdx.x * IMGS_PER_BLOCK;   // first global image of block

    // B is a multiple of IMGS_PER_BLOCK -> block never straddles img1/img2.
    const float4* __restrict__ src = (const float4*)(
        (g0 < (long)nimg) ? (img1 + g0 * 64)
                          : (img2 + (g0 - (long)nimg) * 64));

    // Load weights (tiny, broadcast later from SMEM)
    if (tid < 32) {
        if (tid < 16) sWc[tid]      = ((const float4*)Wc)[tid];
        else          sWl[tid - 16] = ((const float4*)Wl)[tid - 16];
    }

    // Coalesced staging: 128 images * 16 float4 = 2048 float4 per block.
    // f = tid + k*128 -> contiguous global float4 index; scatter into padded smem.
    #pragma unroll
    for (int k = 0; k < F4_PER_IMG; ++k) {
        int f = tid + k * THREADS;
        simg[(f >> 4) * IMG_STRIDE4 + (f & 15)] = src[f];
    }
    __syncthreads();

    const float4* __restrict__ im = &simg[tid * IMG_STRIDE4];

    // Stage 1: acc1[q][j] = sum_i patch[q][i] * Wc[i][j], i = r*4+c ascending.
    // Image row r (8 floats) = float4 pair (2r = cols0-3, 2r+1 = cols4-7).
    // TL: rows 0-3 left | TR: rows 0-3 right | BL: rows 4-7 left | BR: rows 4-7 right.
    float4 a0 = make_float4(0.f, 0.f, 0.f, 0.f);  // TL accum over j
    float4 a1 = a0, a2 = a0, a3 = a0;             // TR, BL, BR

    #pragma unroll
    for (int r = 0; r < 4; ++r) {
        float4 tl = im[2 * r];
        float4 tr = im[2 * r + 1];
        float4 bl = im[2 * r + 8];
        float4 br = im[2 * r + 9];
        const float* ptl = (const float*)&tl;
        const float* ptr_ = (const float*)&tr;
        const float* pbl = (const float*)&bl;
        const float* pbr = (const float*)&br;
        #pragma unroll
        for (int c = 0; c < 4; ++c) {
            float4 w = sWc[r * 4 + c];   // broadcast LDS
            float vtl = ptl[c], vtr = ptr_[c], vbl = pbl[c], vbr = pbr[c];
            a0.x = fmaf(vtl, w.x, a0.x); a0.y = fmaf(vtl, w.y, a0.y);
            a0.z = fmaf(vtl, w.z, a0.z); a0.w = fmaf(vtl, w.w, a0.w);
            a1.x = fmaf(vtr, w.x, a1.x); a1.y = fmaf(vtr, w.y, a1.y);
            a1.z = fmaf(vtr, w.z, a1.z); a1.w = fmaf(vtr, w.w, a1.w);
            a2.x = fmaf(vbl, w.x, a2.x); a2.y = fmaf(vbl, w.y, a2.y);
            a2.z = fmaf(vbl, w.z, a2.z); a2.w = fmaf(vbl, w.w, a2.w);
            a3.x = fmaf(vbr, w.x, a3.x); a3.y = fmaf(vbr, w.y, a3.y);
            a3.z = fmaf(vbr, w.z, a3.z); a3.w = fmaf(vbr, w.w, a3.w);
        }
    }

    // Stage 2: c[k] = clip(relu(acc1)/64), acc2[n] = sum_k c[k]*Wl[k][n], k ascending.
    const float inv64 = 0.015625f;
    float4 acc = make_float4(0.f, 0.f, 0.f, 0.f);
    float4 aq[4] = {a0, a1, a2, a3};
    #pragma unroll
    for (int q = 0; q < 4; ++q) {
        float cx = fminf(fmaxf(aq[q].x, 0.f) * inv64, 127.f);
        float cy = fminf(fmaxf(aq[q].y, 0.f) * inv64, 127.f);
        float cz = fminf(fmaxf(aq[q].z, 0.f) * inv64, 127.f);
        float cw = fminf(fmaxf(aq[q].w, 0.f) * inv64, 127.f);
        float4 w0 = sWl[q * 4 + 0];
        float4 w1 = sWl[q * 4 + 1];
        float4 w2 = sWl[q * 4 + 2];
        float4 w3 = sWl[q * 4 + 3];
        acc.x = fmaf(cx, w0.x, acc.x); acc.y = fmaf(cx, w0.y, acc.y);
        acc.z = fmaf(cx, w0.z, acc.z); acc.w = fmaf(cx, w0.w, acc.w);
        acc.x = fmaf(cy, w1.x, acc.x); acc.y = fmaf(cy, w1.y, acc.y);
        acc.z = fmaf(cy, w1.z, acc.z); acc.w = fmaf(cy, w1.w, acc.w);
        acc.x = fmaf(cz, w2.x, acc.x); acc.y = fmaf(cz, w2.y, acc.y);
        acc.z = fmaf(cz, w2.z, acc.z); acc.w = fmaf(cz, w2.w, acc.w);
        acc.x = fmaf(cw, w3.x, acc.x); acc.y = fmaf(cw, w3.y, acc.y);
        acc.z = fmaf(cw, w3.z, acc.z); acc.w = fmaf(cw, w3.w, acc.w);
    }

    float4 o;
    o.x = clip_s8(acc.x * inv64);
    o.y = clip_s8(acc.y * inv64);
    o.z = clip_s8(acc.z * inv64);
    o.w = clip_s8(acc.w * inv64);

    // out layout: concat(out1, out2) => global image g writes d_out[g*4 .. g*4+3]
    ((float4*)out)[g0 + tid] = o;
}

extern "C" void kernel_launch(void* const* d_in, const int* in_sizes, int n_in,
                              void* d_out, int out_size) {
    const float* img1 = (const float*)d_in[0];
    const float* img2 = (const float*)d_in[1];
    const float* Wc   = (const float*)d_in[2];
    const float* Wl   = (const float*)d_in[3];
    float* out        = (float*)d_out;

    int nimg = in_sizes[0] / 64;              // images per tensor (B)
    long total = 2L * (long)nimg;             // both tensors
    int nblocks = (int)((total + IMGS_PER_BLOCK - 1) / IMGS_PER_BLOCK);

    surrogate_kernel<<<nblocks, THREADS>>>(img1, img2, Wc, Wl, out, nimg);
}

// round 5
// speedup vs baseline: 1.1891x; 1.1891x over previous
#include <cuda_runtime.h>

// Float32HardwareSurrogate — zero-SMEM warp-shuffle version.
//
// Key fact: a warp issuing coalesced float4 loads (idx = lane + 32k over an
// image-contiguous region, 16 float4 per 8x8 image) naturally yields, at each
// iteration k, one COMPLETE image per 16-lane group:
//   lanes 0-15  hold the 16 float4 elements of image 2k   (lane e -> elem e)
//   lanes 16-31 hold the 16 float4 elements of image 2k+1
// Element e: row r=e>>1, half h=e&1 -> quadrant q = ((e>>3)<<1)|(e&1),
// quadrant-row rr=(r&3), pixels = quadrant row rr cols 0..3.
//
// Stage 1 (per lane): P[j] = sum_c v[c]*Wc[rr*4+c][j]  (float4 over channels j)
// Reduce-SCATTER over the 4 holder lanes of each quadrant (xor 4 then xor 2,
// 3 shuffles total) -> lane e ends with the single scalar c[K], K = q*4+rr.
// All 16 lanes hold exactly one distinct c component (bijection).
// Stage 2 (per lane): T = clip(relu(c)/64) * Wl[K][:]  (float4 over outputs n)
// Reduce-scatter over 16 lanes (xor 8,4,2,1; 5 shuffles) -> lanes e with
// e&3==0 hold output component n = 2*((e>>3)&1)+((e>>2)&1), replicated x4.
// Predicated STG.32 from 8 lanes writes 32 contiguous bytes (1 wavefront).
//
// No shared memory, no barriers -> occupancy limited only by regs (64 cap).

#define THREADS 256
#define WARPS_PER_BLOCK 8
#define IMGS_PER_WARP 32

__global__ void __launch_bounds__(THREADS, 4)
surrogate_kernel(const float* __restrict__ img1,
                 const float* __restrict__ img2,
                 const float* __restrict__ Wc,
                 const float* __restrict__ Wl,
                 float* __restrict__ out,
                 int nimg)
{
    const int lane = threadIdx.x & 31;
    const int warp = threadIdx.x >> 5;
    const long wg  = (long)blockIdx.x * WARPS_PER_BLOCK + warp;
    const long g0  = wg * IMGS_PER_WARP;          // first global image of warp
    const long total = 2L * (long)nimg;
    if (g0 >= total) return;

    // nimg is a multiple of 32 -> warp never straddles img1/img2.
    const float4* __restrict__ src = (const float4*)(
        (g0 < (long)nimg) ? (img1 + g0 * 64)
                          : (img2 + (g0 - (long)nimg) * 64));

    // ---- per-lane constants ----
    const int e    = lane & 15;
    const int g    = lane >> 4;                   // image parity within pair
    const int rr   = (e >> 1) & 3;                // row within quadrant
    const int q    = ((e >> 3) << 1) | (e & 1);   // quadrant TL,TR,BL,BR
    const int K    = q * 4 + rr;                  // c-vector index this lane owns
    const int sel2 = (rr >> 1) & 1;               // stage-1 scatter selectors
    const int sel1 = rr & 1;
    const int selA = (e >> 3) & 1;                // stage-2 scatter selectors
    const int selB = (e >> 2) & 1;
    const int ncomp = 2 * selA + selB;            // output component this lane ends with
    const bool do_store = ((e & 3) == 0);

    // ---- weights into registers (L2/L1 broadcast hits) ----
    const float4* Wc4 = (const float4*)Wc;        // row i = Wc[i][0..3]
    const float4* Wl4 = (const float4*)Wl;
    const float4 wc0 = Wc4[rr * 4 + 0];
    const float4 wc1 = Wc4[rr * 4 + 1];
    const float4 wc2 = Wc4[rr * 4 + 2];
    const float4 wc3 = Wc4[rr * 4 + 3];
    const float4 wl  = Wl4[K];

    const float inv64 = 0.015625f;
    float* __restrict__ outf = out;
    const unsigned FULL = 0xffffffffu;

    // 16 iterations, loads batched in groups of 4 for MLP.
    #pragma unroll
    for (int kb = 0; kb < 4; ++kb) {
        float4 v[4];
        #pragma unroll
        for (int t = 0; t < 4; ++t)
            v[t] = src[lane + 32 * (kb * 4 + t)];

        #pragma unroll
        for (int t = 0; t < 4; ++t) {
            const int k = kb * 4 + t;

            // Stage 1 partial: P[j] over 4 conv channels
            float4 P;
            P.x = v[t].x * wc0.x; P.y = v[t].x * wc0.y;
            P.z = v[t].x * wc0.z; P.w = v[t].x * wc0.w;
            P.x = fmaf(v[t].y, wc1.x, P.x); P.y = fmaf(v[t].y, wc1.y, P.y);
            P.z = fmaf(v[t].y, wc1.z, P.z); P.w = fmaf(v[t].y, wc1.w, P.w);
            P.x = fmaf(v[t].z, wc2.x, P.x); P.y = fmaf(v[t].z, wc2.y, P.y);
            P.z = fmaf(v[t].z, wc2.z, P.z); P.w = fmaf(v[t].z, wc2.w, P.w);
            P.x = fmaf(v[t].w, wc3.x, P.x); P.y = fmaf(v[t].w, wc3.y, P.y);
            P.z = fmaf(v[t].w, wc3.z, P.z); P.w = fmaf(v[t].w, wc3.w, P.w);

            // Reduce-scatter over quadrant holder lanes {e, e^2, e^4, e^6}
            // step A: xor 4 — keep channel pair selected by sel2, send other
            float sA = sel2 ? P.x : P.z;
            float sB = sel2 ? P.y : P.w;
            float rA = __shfl_xor_sync(FULL, sA, 4);
            float rB = __shfl_xor_sync(FULL, sB, 4);
            float A  = (sel2 ? P.z : P.x) + rA;
            float Bv = (sel2 ? P.w : P.y) + rB;
            // step B: xor 2 — keep single channel selected by sel1
            float sC = sel1 ? A : Bv;
            float rC = __shfl_xor_sync(FULL, sC, 2);
            float c1 = (sel1 ? Bv : A) + rC;

            // nonlinearity: relu -> /64 -> clip upper (lower clip dead after relu)
            float cv = fminf(fmaxf(c1, 0.0f) * inv64, 127.0f);

            // Stage 2 partial: T[n] = cv * Wl[K][n]
            float4 T;
            T.x = cv * wl.x; T.y = cv * wl.y; T.z = cv * wl.z; T.w = cv * wl.w;

            // Reduce-scatter over the 16-lane group
            // xor 8: keep output pair by selA
            float tA = selA ? T.x : T.z;
            float tB = selA ? T.y : T.w;
            float uA = __shfl_xor_sync(FULL, tA, 8);
            float uB = __shfl_xor_sync(FULL, tB, 8);
            float A2 = (selA ? T.z : T.x) + uA;
            float B2 = (selA ? T.w : T.y) + uB;
            // xor 4: keep single output by selB
            float tC = selB ? A2 : B2;
            float uC = __shfl_xor_sync(FULL, tC, 4);
            float sc = (selB ? B2 : A2) + uC;
            // xor 2, xor 1: plain reduce (same component within these lanes)
            sc += __shfl_xor_sync(FULL, sc, 2);
            sc += __shfl_xor_sync(FULL, sc, 1);

            float o = fminf(fmaxf(sc * inv64, -128.0f), 127.0f);

            // lanes {0,4,8,12}(+16) store components 0..3 of images 2k, 2k+1:
            // 8 active lanes, 32 contiguous bytes -> 1 wavefront
            if (do_store)
                outf[(g0 + 2 * k + g) * 4 + ncomp] = o;
        }
    }
}

extern "C" void kernel_launch(void* const* d_in, const int* in_sizes, int n_in,
                              void* d_out, int out_size) {
    const float* img1 = (const float*)d_in[0];
    const float* img2 = (const float*)d_in[1];
    const float* Wc   = (const float*)d_in[2];
    const float* Wl   = (const float*)d_in[3];
    float* out        = (float*)d_out;

    int nimg = in_sizes[0] / 64;                       // B
    long total_imgs = 2L * (long)nimg;
    long total_warps = (total_imgs + IMGS_PER_WARP - 1) / IMGS_PER_WARP;
    int nblocks = (int)((total_warps + WARPS_PER_BLOCK - 1) / WARPS_PER_BLOCK);

    surrogate_kernel<<<nblocks, THREADS>>>(img1, img2, Wc, Wl, out, nimg);
}